// round 2
// baseline (speedup 1.0000x reference)
#include <cuda_runtime.h>
#include <math.h>

#define NBATCH 4
#define LTOK   4096
#define CDIM   256
#define NHEAD  8
#define NTOPIC 100
#define NSAMP  6

// ======================= device scratch =======================
__device__ float g_f0[NBATCH*LTOK*CDIM];
__device__ float g_f1[NBATCH*LTOK*CDIM];
__device__ float g_fo[NBATCH*2*LTOK*CDIM];
__device__ float g_seeds[NBATCH*NTOPIC*CDIM];
__device__ float g_seedsF[NBATCH*NTOPIC*CDIM];
__device__ float g_nf0[NBATCH*LTOK*CDIM];
__device__ float g_nf1[NBATCH*LTOK*CDIM];
__device__ float g_q[NBATCH*LTOK*CDIM];
__device__ float g_k[NBATCH*2*LTOK*CDIM];
__device__ float g_v[NBATCH*2*LTOK*CDIM];
__device__ float g_msg[NBATCH*LTOK*CDIM];
__device__ float g_cat[NBATCH*LTOK*2*CDIM];
__device__ float g_hid[NBATCH*LTOK*2*CDIM];
__device__ float g_ffn[NBATCH*LTOK*CDIM];
__device__ float g_KV[NBATCH*NHEAD*32*32];
__device__ float g_Ksum[NBATCH*NHEAD*32];
__device__ float g_dm[NBATCH*2*LTOK*NTOPIC];
__device__ float g_tm[NBATCH*NTOPIC*NTOPIC];
__device__ float g_cmax[NBATCH*NTOPIC];
__device__ float g_csum[NBATCH*NTOPIC];
__device__ float g_topic[NBATCH*NTOPIC*96];
__device__ float g_sumh[2*NBATCH*NTOPIC];
__device__ float g_cond[NSAMP];
__device__ int   g_amax[NBATCH*2*LTOK];
__device__ int   g_tmidx[NBATCH*NTOPIC];
__device__ int   g_inds[NBATCH*NSAMP];
__device__ int   g_sel[2*NSAMP*NBATCH*LTOK];
__device__ int   g_cnt[2*NSAMP*NBATCH];

// ======================= generic =======================
__global__ void zero_k(float* p, long n){
    long i=(long)blockIdx.x*blockDim.x+threadIdx.x; if(i<n) p[i]=0.f;
}
__global__ void copy_k(float* d, const float* s, long n){
    long i=(long)blockIdx.x*blockDim.x+threadIdx.x; if(i<n) d[i]=s[i];
}
__global__ void bcast_seeds_k(const float* st){
    long i=(long)blockIdx.x*blockDim.x+threadIdx.x;
    long tot=(long)NBATCH*NTOPIC*CDIM;
    if(i<tot) g_seeds[i]=st[i%(NTOPIC*CDIM)];
}
__global__ void concatfeat_k(const float* f0, const float* f1){
    long i=(long)blockIdx.x*blockDim.x+threadIdx.x;
    long tot=(long)NBATCH*2*LTOK*CDIM; if(i>=tot) return;
    int n=(int)(i/(2L*LTOK*CDIM));
    long rem=i-(long)n*2*LTOK*CDIM;
    int row=(int)(rem/CDIM); int c=(int)(rem-(long)row*CDIM);
    if(row<LTOK) g_fo[i]=f0[((long)n*LTOK+row)*CDIM+c];
    else         g_fo[i]=f1[((long)n*LTOK+row-LTOK)*CDIM+c];
}

// ---- SGEMM  C[M,N] = epi(alpha * A[M,K] @ B) ----
// EPI: 0 none, 1 elu+1, 2 relu. transB: B is (N,K) rm, else (K,N) rm, ld=ldB.
// counts non-null: per-batch valid rows (rowsPerBatch rows/batch, mult of 64) -> tile early-exit.
template<int EPI>
__global__ void __launch_bounds__(256) sgemm_k(
    const float* __restrict__ A, const float* __restrict__ B, float* __restrict__ Cm,
    int M,int N,int K,int transB,int ldB,long strideB,
    int rowsPerBatch,const int* __restrict__ counts,float alpha)
{
    int bm=blockIdx.y*64, bn=blockIdx.x*64;
    if(counts){ int nb=bm/rowsPerBatch; if((bm-nb*rowsPerBatch)>=counts[nb]) return; }
    const float* Bp=B;
    if(strideB) Bp += (long)(bm/rowsPerBatch)*strideB;

    __shared__ float As[16][68];
    __shared__ float Bs[16][68];
    int tid=threadIdx.x, tx=tid&15, ty=tid>>4;
    float acc[4][4]={};

    for(int k0=0;k0<K;k0+=16){
        #pragma unroll
        for(int t=0;t<4;t++){
            int idx=tid+t*256; int kk=idx&15, mm=idx>>4;
            int gr=bm+mm;
            As[kk][mm]=(gr<M)?A[(long)gr*K+k0+kk]:0.f;
        }
        if(!transB){
            #pragma unroll
            for(int t=0;t<4;t++){
                int idx=tid+t*256; int nn=idx&63, kk=idx>>6;
                int gc=bn+nn;
                Bs[kk][nn]=(gc<N)?Bp[(long)(k0+kk)*ldB+gc]:0.f;
            }
        } else {
            #pragma unroll
            for(int t=0;t<4;t++){
                int idx=tid+t*256; int kk=idx&15, nn=idx>>4;
                int gc=bn+nn;
                Bs[kk][nn]=(gc<N)?Bp[(long)gc*ldB+k0+kk]:0.f;
            }
        }
        __syncthreads();
        #pragma unroll
        for(int kk=0;kk<16;kk++){
            float4 a4=*(const float4*)&As[kk][ty*4];
            float4 b4=*(const float4*)&Bs[kk][tx*4];
            float a[4]={a4.x,a4.y,a4.z,a4.w};
            float b[4]={b4.x,b4.y,b4.z,b4.w};
            #pragma unroll
            for(int i=0;i<4;i++)
                #pragma unroll
                for(int j=0;j<4;j++) acc[i][j]=fmaf(a[i],b[j],acc[i][j]);
        }
        __syncthreads();
    }
    #pragma unroll
    for(int i=0;i<4;i++){
        int gr=bm+ty*4+i; if(gr>=M) continue;
        #pragma unroll
        for(int j=0;j<4;j++){
            int gc=bn+tx*4+j; if(gc>=N) continue;
            float vv=acc[i][j]*alpha;
            if(EPI==1){ vv=(vv>0.f)?vv:expm1f(vv); vv+=1.f; }
            else if(EPI==2){ vv=fmaxf(vv,0.f); }
            Cm[(long)gr*N+gc]=vv;
        }
    }
}

// ---- KV[n,h,d,v] += sum_s K[s]V[s];  Ksum[n,h,d] += sum_s K[s] ----
__global__ void __launch_bounds__(256) kv_reduce_k(
    const float* __restrict__ Kp,const float* __restrict__ Vp,
    float* __restrict__ KV,float* __restrict__ Ksum,
    int Ls,int chunkRows,const int* __restrict__ counts)
{
    int nh=blockIdx.y; int n=nh>>3, h=nh&7;
    int cnt=counts?counts[n]:Ls; if(cnt>Ls) cnt=Ls;
    int rstart=blockIdx.x*chunkRows; if(rstart>=cnt) return;
    int rend=min(rstart+chunkRows,cnt);

    __shared__ float sK[32][33];
    __shared__ float sV[32][33];
    int tid=threadIdx.x;
    int d=tid>>3, vb=(tid&7)*4;
    float acc[4]={0,0,0,0}; float ksumAcc=0.f;
    long rowBase=(long)n*Ls;

    for(int r0=rstart;r0<rend;r0+=32){
        #pragma unroll
        for(int t=0;t<8;t++){
            int idx=tid+t*256; int rr=idx>>6, cc=idx&63;
            int grow=r0+rr; float val=0.f;
            if(grow<rend){
                long base=(rowBase+grow)*CDIM+h*32;
                val=(cc<32)?Kp[base+cc]:Vp[base+cc-32];
            }
            if(cc<32) sK[rr][cc]=val; else sV[rr][cc-32]=val;
        }
        __syncthreads();
        int nr=min(32,rend-r0);
        for(int r=0;r<nr;r++){
            float kv=sK[r][d];
            #pragma unroll
            for(int j=0;j<4;j++) acc[j]=fmaf(kv,sV[r][vb+j],acc[j]);
        }
        if(tid<32) for(int r=0;r<nr;r++) ksumAcc+=sK[r][tid];
        __syncthreads();
    }
    long ob=(long)nh*1024;
    #pragma unroll
    for(int j=0;j<4;j++) atomicAdd(&KV[ob+d*32+vb+j],acc[j]);
    if(tid<32) atomicAdd(&Ksum[(long)nh*32+tid],ksumAcc);
}

// ---- msg[l,h,v] = (Q[l,h,:]·KV[h,:,v]) / (Q[l,h,:]·Ksum[h,:] + 1e-6) ----
__global__ void __launch_bounds__(256) msg_k(
    const float* __restrict__ Q,const float* __restrict__ KV,
    const float* __restrict__ Ksum,float* __restrict__ Msg,
    int Lx,const int* __restrict__ counts)
{
    int row=blockIdx.x; int n=row/Lx;
    if(counts && (row-n*Lx)>=counts[n]) return;
    __shared__ float qs[256]; __shared__ float zinv[8];
    int t=threadIdx.x;
    float qv=Q[(long)row*CDIM+t]; qs[t]=qv;
    int h=t>>5, lane=t&31;
    float p=qv*Ksum[(n*8+h)*32+lane];
    #pragma unroll
    for(int o=16;o>0;o>>=1) p+=__shfl_xor_sync(0xffffffffu,p,o);
    if(lane==0) zinv[h]=1.f/(p+1e-6f);
    __syncthreads();
    const float* kvb=KV+(long)(n*8+h)*1024;
    float acc=0.f;
    #pragma unroll
    for(int d=0;d<32;d++) acc=fmaf(qs[h*32+d],kvb[d*32+lane],acc);
    Msg[(long)row*CDIM+t]=acc*zinv[h];
}

__device__ __forceinline__ float blockSum256(float v,float* red){
    #pragma unroll
    for(int o=16;o>0;o>>=1) v+=__shfl_xor_sync(0xffffffffu,v,o);
    int t=threadIdx.x;
    if((t&31)==0) red[t>>5]=v;
    __syncthreads();
    float s=red[0]+red[1]+red[2]+red[3]+red[4]+red[5]+red[6]+red[7];
    __syncthreads();
    return s;
}

// layernorm(256). addTo!=null: addTo += ln(X); else Y = ln(X)
__global__ void __launch_bounds__(256) ln_k(
    const float* __restrict__ X,float* __restrict__ Y,float* __restrict__ addTo,
    int Lx,const int* __restrict__ counts,float eps)
{
    int row=blockIdx.x; int n=row/Lx;
    if(counts && (row-n*Lx)>=counts[n]) return;
    __shared__ float red[8];
    int t=threadIdx.x;
    long off=(long)row*CDIM+t;
    float v=X[off];
    float mu=blockSum256(v,red)*(1.f/256.f);
    float dv=v-mu;
    float var=blockSum256(dv*dv,red)*(1.f/256.f);
    float y=dv*rsqrtf(var+eps);
    if(addTo) addTo[off]+=y; else Y[off]=y;
}

__global__ void __launch_bounds__(256) concat_k(
    const float* __restrict__ X,const float* __restrict__ Msg,float* __restrict__ Cat,
    int Lx,const int* __restrict__ counts)
{
    int row=blockIdx.x; int n=row/Lx;
    if(counts && (row-n*Lx)>=counts[n]) return;
    int t=threadIdx.x;
    Cat[(long)row*512+t]=X[(long)row*CDIM+t];
    Cat[(long)row*512+256+t]=Msg[(long)row*CDIM+t];
}

// ======================= topic preprocessing =======================
__global__ void tm_k(const float* __restrict__ t0r,const float* __restrict__ t1r){
    int b=blockIdx.x; int n=b/NTOPIC, m=b%NTOPIC;
    int k=threadIdx.x; if(k>=NTOPIC) return;
    const float* p0=t0r+(long)n*96*NTOPIC;
    const float* p1=t1r+(long)n*96*NTOPIC;
    float s=0.f;
    for(int d=0;d<96;d++) s+=p0[d*NTOPIC+m]*p1[d*NTOPIC+k];
    g_tm[(long)b*NTOPIC+k]=floorf(s*0.0625f);
}
__global__ void colstat_k(){
    int n=blockIdx.x; int l=threadIdx.x; if(l>=NTOPIC) return;
    const float* p=g_tm+(long)n*NTOPIC*NTOPIC;
    float mx=-1e30f;
    for(int m=0;m<NTOPIC;m++) mx=fmaxf(mx,p[m*NTOPIC+l]);
    float s=0.f;
    for(int m=0;m<NTOPIC;m++) s+=expf(p[m*NTOPIC+l]-mx);
    g_cmax[n*NTOPIC+l]=mx; g_csum[n*NTOPIC+l]=s;
}
__global__ void tmidx_k(){
    if(threadIdx.x!=0) return;
    int b=blockIdx.x; int n=b/NTOPIC;
    const float* p=g_tm+(long)b*NTOPIC;
    float rmx=-1e30f;
    for(int l=0;l<NTOPIC;l++) rmx=fmaxf(rmx,p[l]);
    float rs=0.f;
    for(int l=0;l<NTOPIC;l++) rs+=expf(p[l]-rmx);
    float best=-1e30f; int bi=0;
    for(int l=0;l<NTOPIC;l++){
        float v=(expf(p[l]-rmx)/rs)*(expf(p[l]-g_cmax[n*NTOPIC+l])/g_csum[n*NTOPIC+l]);
        if(v>best){best=v;bi=l;}
    }
    g_tmidx[b]=bi;
}
__global__ void topic_k(const float* __restrict__ topic0,const float* __restrict__ topic1){
    int b=blockIdx.x; int n=b/NTOPIC, m=b%NTOPIC;
    int j=threadIdx.x; if(j>=96) return;
    int idx=g_tmidx[(NBATCH-1)*NTOPIC+m];
    float v;
    if(j<48){
        const float* p0=topic0+(long)n*96*NTOPIC;
        v=0.5f*(p0[(2*j)*NTOPIC+m]+p0[(2*j+1)*NTOPIC+m]);
    }else{
        int d0=2*j-96;
        const float* p1=topic1+(long)n*96*NTOPIC;
        v=0.5f*(p1[d0*NTOPIC+idx]+p1[(d0+1)*NTOPIC+idx]);
    }
    g_topic[(long)b*96+j]=v;
}
// seeds pool 256->160 + concat topic(96) + layernorm(1e-5)
__global__ void __launch_bounds__(256) seedfin_k(){
    int row=blockIdx.x; int t=threadIdx.x;
    __shared__ float red[8];
    float v;
    if(t<160){
        int s=t*256/160;
        int e=((t+1)*256+159)/160;
        float acc=0.f;
        for(int i=s;i<e;i++) acc+=g_seeds[(long)row*CDIM+i];
        v=acc/(float)(e-s);
    }else v=g_topic[(long)row*96+(t-160)];
    float mu=blockSum256(v,red)*(1.f/256.f);
    float dv=v-mu;
    float var=blockSum256(dv*dv,red)*(1.f/256.f);
    g_seedsF[(long)row*CDIM+t]=dv*rsqrtf(var+1e-5f);
}

// ======================= dmatrix stats =======================
__global__ void __launch_bounds__(64) prob_k(){
    __shared__ float s[NTOPIC];
    int t=threadIdx.x;
    for(int i=t;i<NTOPIC;i+=64) s[i]=0.f;
    __syncthreads();
    int row=blockIdx.x*64+t;
    const float* dr=g_dm+(long)row*NTOPIC;
    float mx=dr[0]; int ai=0;
    for(int k=1;k<NTOPIC;k++){ float v=dr[k]; if(v>mx){mx=v;ai=k;} }
    g_amax[row]=ai;
    float se=0.f;
    for(int k=0;k<NTOPIC;k++) se+=expf(dr[k]-mx);
    float inv=1.f/se;
    for(int kk=0;kk<NTOPIC;kk++){
        int k=(t+kk)%NTOPIC;
        atomicAdd(&s[k],expf(dr[k]-mx)*inv);
    }
    __syncthreads();
    int n=row/(2*LTOK);
    int half=(row%(2*LTOK))/LTOK;
    float* outp=g_sumh+((long)(half*NBATCH+n)*NTOPIC);
    for(int i=t;i<NTOPIC;i+=64) atomicAdd(&outp[i],s[i]);
}
__global__ void theta_k(){
    if(threadIdx.x!=0) return;
    int n=blockIdx.x;
    float a[NTOPIC],b[NTOPIC],th[NTOPIC];
    float sa=0.f,sb=0.f;
    for(int k=0;k<NTOPIC;k++){a[k]=g_sumh[(0*NBATCH+n)*NTOPIC+k];sa+=fabsf(a[k]);}
    for(int k=0;k<NTOPIC;k++){b[k]=g_sumh[(1*NBATCH+n)*NTOPIC+k];sb+=fabsf(b[k]);}
    sa=fmaxf(sa,1e-12f); sb=fmaxf(sb,1e-12f);
    for(int k=0;k<NTOPIC;k++) th[k]=(a[k]/sa)*(b[k]/sb);
    bool used[NTOPIC];
    for(int k=0;k<NTOPIC;k++) used[k]=false;
    for(int kk=0;kk<NSAMP;kk++){
        float best=-1e30f; int bi=0;
        for(int k=0;k<NTOPIC;k++) if(!used[k]&&th[k]>best){best=th[k];bi=k;}
        used[bi]=true; g_inds[n*NSAMP+kk]=bi;
    }
}
__global__ void selbuild_k(){
    if(threadIdx.x!=0) return;
    int b=blockIdx.x;               // slot = (kk*2+half)*NBATCH + n  ordering below
    int kk=b/(2*NBATCH);
    int half=(b/NBATCH)%2;
    int n=b%NBATCH;
    int topic=g_inds[n*NSAMP+kk];
    const int* am=g_amax+n*2*LTOK+half*LTOK;
    int c=0; int* sl=g_sel+(long)b*LTOK;
    for(int l=0;l<LTOK;l++) if(am[l]==topic) sl[c++]=l;
    g_cnt[b]=c;
}
__global__ void cond_k(){
    int kk=threadIdx.x; if(kk>=NSAMP) return;
    int s0=0,s1=0;
    for(int n=0;n<NBATCH;n++){
        s0+=g_cnt[(kk*2+0)*NBATCH+n];
        s1+=g_cnt[(kk*2+1)*NBATCH+n];
    }
    g_cond[kk]=(s0>0&&s1>0)?1.f:0.f;
}
__global__ void gather_k(float* __restrict__ dst,const float* __restrict__ srcF,int slot){
    int j=blockIdx.x, n=blockIdx.y;
    if(j>=g_cnt[slot*NBATCH+n]) return;
    int l=g_sel[((long)slot*NBATCH+n)*LTOK+j];
    dst[((long)n*LTOK+j)*CDIM+threadIdx.x]=srcF[((long)n*LTOK+l)*CDIM+threadIdx.x];
}
__global__ void scatter_k(float* __restrict__ outF,const float* __restrict__ nf,int slot,int kk){
    int j=blockIdx.x, n=blockIdx.y;
    if(j>=g_cnt[slot*NBATCH+n]) return;
    int l=g_sel[((long)slot*NBATCH+n)*LTOK+j];
    float c=g_cond[kk];
    outF[((long)n*LTOK+l)*CDIM+threadIdx.x]+=nf[((long)n*LTOK+j)*CDIM+threadIdx.x]*c;
}
__global__ void blend_k(float* __restrict__ outF,const float* __restrict__ fcur,int half){
    int r=blockIdx.x; int n=r/LTOK, l=r%LTOK;
    int am=g_amax[n*2*LTOK+half*LTOK+l];
    int issel=0;
    for(int kk=0;kk<NSAMP;kk++) if(am==g_inds[n*NSAMP+kk]) issel=1;
    if(!issel){
        int t=threadIdx.x;
        outF[(long)r*CDIM+t]+=fcur[(long)r*CDIM+t];
    }
}
// neigh_mean: x4 = dm(half) flat reinterpreted (K,64,64); 3x3 zero-pad box mean; out = dm*poolT
__global__ void tmi_k(int half,float* __restrict__ out){
    int nk=blockIdx.x; int n=nk/NTOPIC, k=nk%NTOPIC;
    int h=blockIdx.y, w=threadIdx.x;
    const float* base=g_dm+(long)n*2*LTOK*NTOPIC+(long)half*LTOK*NTOPIC;
    float acc=0.f;
    for(int dh=-1;dh<=1;dh++){
        int hh=h+dh; if(hh<0||hh>=64) continue;
        for(int dw=-1;dw<=1;dw++){
            int ww=w+dw; if(ww<0||ww>=64) continue;
            acc+=base[k*4096+hh*64+ww];
        }
    }
    acc*=(1.f/9.f);
    int l=h*64+w;
    out[((long)n*LTOK+l)*NTOPIC+k]=base[(long)l*NTOPIC+k]*acc;
}

// ======================= host side =======================
static void run_gemm(const float* A,const float* B,float* C,int M,int N,int K,
                     int transB,int ldB,long strideB,int rpb,const int* counts,
                     float alpha,int epi)
{
    dim3 g((N+63)/64,(M+63)/64);
    if(epi==0)      sgemm_k<0><<<g,256>>>(A,B,C,M,N,K,transB,ldB,strideB,rpb,counts,alpha);
    else if(epi==1) sgemm_k<1><<<g,256>>>(A,B,C,M,N,K,transB,ldB,strideB,rpb,counts,alpha);
    else            sgemm_k<2><<<g,256>>>(A,B,C,M,N,K,transB,ldB,strideB,rpb,counts,alpha);
}

struct Ptrs {
    float *f0,*f1,*fo,*seeds,*seedsF,*nf0,*nf1,*q,*k,*v,*msg,*cat,*hid,*ffn,*KV,*Ksum,*dm,*sumh;
    int *cnt;
};

static void enc_layer(Ptrs& P,float* x,const float* src,int rpbX,int rpbS,
                      const int* cx,const int* cs,
                      const float* Wq,const float* Wk,const float* Wv,
                      const float* Wm,const float* W1,const float* W2)
{
    int Mx=NBATCH*rpbX, Ms=NBATCH*rpbS;
    run_gemm(x,  Wq,P.q,Mx,256,256,0,256,0,rpbX,cx,1.f,1);
    run_gemm(src,Wk,P.k,Ms,256,256,0,256,0,rpbS,cs,1.f,1);
    run_gemm(src,Wv,P.v,Ms,256,256,0,256,0,rpbS,cs,1.f,0);
    zero_k<<<(NBATCH*NHEAD*1024+255)/256,256>>>(P.KV,NBATCH*NHEAD*1024);
    zero_k<<<(NBATCH*NHEAD*32+255)/256,256>>>(P.Ksum,NBATCH*NHEAD*32);
    int chunk=512;
    dim3 gkv((rpbS+chunk-1)/chunk,NBATCH*NHEAD);
    kv_reduce_k<<<gkv,256>>>(P.k,P.v,P.KV,P.Ksum,rpbS,chunk,cs);
    msg_k<<<Mx,256>>>(P.q,P.KV,P.Ksum,P.msg,rpbX,cx);
    run_gemm(P.msg,Wm,P.ffn,Mx,256,256,0,256,0,rpbX,cx,1.f,0);
    ln_k<<<Mx,256>>>(P.ffn,P.msg,nullptr,rpbX,cx,1e-5f);
    concat_k<<<Mx,256>>>(x,P.msg,P.cat,rpbX,cx);
    run_gemm(P.cat,W1,P.hid,Mx,512,512,0,512,0,rpbX,cx,1.f,2);
    run_gemm(P.hid,W2,P.ffn,Mx,256,512,0,256,0,rpbX,cx,1.f,0);
    ln_k<<<Mx,256>>>(P.ffn,nullptr,x,rpbX,cx,1e-5f);
}

extern "C" void kernel_launch(void* const* d_in, const int* in_sizes, int n_in,
                              void* d_out, int out_size)
{
    static Ptrs P; static bool inited=false;
    static int *p_sel=nullptr, *p_amax=nullptr;
    if(!inited){
        cudaGetSymbolAddress((void**)&P.f0,g_f0);
        cudaGetSymbolAddress((void**)&P.f1,g_f1);
        cudaGetSymbolAddress((void**)&P.fo,g_fo);
        cudaGetSymbolAddress((void**)&P.seeds,g_seeds);
        cudaGetSymbolAddress((void**)&P.seedsF,g_seedsF);
        cudaGetSymbolAddress((void**)&P.nf0,g_nf0);
        cudaGetSymbolAddress((void**)&P.nf1,g_nf1);
        cudaGetSymbolAddress((void**)&P.q,g_q);
        cudaGetSymbolAddress((void**)&P.k,g_k);
        cudaGetSymbolAddress((void**)&P.v,g_v);
        cudaGetSymbolAddress((void**)&P.msg,g_msg);
        cudaGetSymbolAddress((void**)&P.cat,g_cat);
        cudaGetSymbolAddress((void**)&P.hid,g_hid);
        cudaGetSymbolAddress((void**)&P.ffn,g_ffn);
        cudaGetSymbolAddress((void**)&P.KV,g_KV);
        cudaGetSymbolAddress((void**)&P.Ksum,g_Ksum);
        cudaGetSymbolAddress((void**)&P.dm,g_dm);
        cudaGetSymbolAddress((void**)&P.sumh,g_sumh);
        cudaGetSymbolAddress((void**)&P.cnt,g_cnt);
        cudaGetSymbolAddress((void**)&p_sel,g_sel);
        cudaGetSymbolAddress((void**)&p_amax,g_amax);
        inited=true;
    }
    const float* in_f0=(const float*)d_in[0];
    const float* in_f1=(const float*)d_in[1];
    const float* in_t0=(const float*)d_in[2];
    const float* in_t1=(const float*)d_in[3];
    const float* in_st=(const float*)d_in[4];
    const float* Wq=(const float*)d_in[5];
    const float* Wk=(const float*)d_in[6];
    const float* Wv=(const float*)d_in[7];
    const float* Wm=(const float*)d_in[8];
    const float* W1=(const float*)d_in[9];
    const float* W2=(const float*)d_in[10];
    float* out=(float*)d_out;

    const long FREG=(long)NBATCH*LTOK*CDIM;          // 4194304
    const long TREG=(long)NBATCH*LTOK*NTOPIC;        // 1638400
    float* out_f0=out;
    float* out_f1=out+FREG;
    float* out_t0=out+2*FREG;
    float* out_t1=out+2*FREG+TREG;

    // --- setup ---
    copy_k<<<(FREG+255)/256,256>>>(P.f0,in_f0,FREG);
    copy_k<<<(FREG+255)/256,256>>>(P.f1,in_f1,FREG);
    concatfeat_k<<<(2*FREG+255)/256,256>>>(in_f0,in_f1);
    bcast_seeds_k<<<(NBATCH*NTOPIC*CDIM+255)/256,256>>>(in_st);

    // --- topic preprocessing ---
    tm_k<<<NBATCH*NTOPIC,128>>>(in_t0,in_t1);
    colstat_k<<<NBATCH,128>>>();
    tmidx_k<<<NBATCH*NTOPIC,32>>>();
    topic_k<<<NBATCH*NTOPIC,96>>>(in_t0,in_t1);

    // --- main encoder stack (weights 0..3) ---
    auto LW=[&](int i,const float*& wq,const float*& wk,const float*& wv,
                const float*& wm,const float*& w1,const float*& w2){
        wq=Wq+(long)i*256*256; wk=Wk+(long)i*256*256; wv=Wv+(long)i*256*256;
        wm=Wm+(long)i*256*256; w1=W1+(long)i*512*512; w2=W2+(long)i*512*256;
    };
    const float *wq,*wk,*wv,*wm,*w1,*w2;
    LW(0,wq,wk,wv,wm,w1,w2);
    enc_layer(P,P.seeds,P.fo,NTOPIC,2*LTOK,nullptr,nullptr,wq,wk,wv,wm,w1,w2);
    LW(1,wq,wk,wv,wm,w1,w2);
    enc_layer(P,P.f0,P.seeds,LTOK,NTOPIC,nullptr,nullptr,wq,wk,wv,wm,w1,w2);
    enc_layer(P,P.f1,P.seeds,LTOK,NTOPIC,nullptr,nullptr,wq,wk,wv,wm,w1,w2);
    LW(2,wq,wk,wv,wm,w1,w2);
    enc_layer(P,P.seeds,P.fo,NTOPIC,2*LTOK,nullptr,nullptr,wq,wk,wv,wm,w1,w2);
    LW(3,wq,wk,wv,wm,w1,w2);
    enc_layer(P,P.f0,P.seeds,LTOK,NTOPIC,nullptr,nullptr,wq,wk,wv,wm,w1,w2);
    enc_layer(P,P.f1,P.seeds,LTOK,NTOPIC,nullptr,nullptr,wq,wk,wv,wm,w1,w2);

    // --- final seeds (pool+topic+ln), dmatrix ---
    seedfin_k<<<NBATCH*NTOPIC,256>>>();
    run_gemm(P.fo,P.seedsF,P.dm,NBATCH*2*LTOK,NTOPIC,256,
             1,256,(long)NTOPIC*256,2*LTOK,nullptr,0.0625f,0);

    // --- prob sums / argmax / topk / selection ---
    zero_k<<<(2*NBATCH*NTOPIC+255)/256,256>>>(P.sumh,2*NBATCH*NTOPIC);
    prob_k<<<(NBATCH*2*LTOK)/64,64>>>();
    theta_k<<<NBATCH,32>>>();
    selbuild_k<<<NSAMP*2*NBATCH,32>>>();
    cond_k<<<1,32>>>();

    // --- zero updated feat regions in out ---
    zero_k<<<(2*FREG+255)/256,256>>>(out_f0,2*FREG);

    // --- refinement samples ---
    for(int kk=0;kk<NSAMP;kk++){
        int s0=kk*2, s1=kk*2+1;
        const int* c0=P.cnt+s0*NBATCH;
        const int* c1=P.cnt+s1*NBATCH;
        gather_k<<<dim3(LTOK,NBATCH),256>>>(P.nf0,P.f0,s0);
        gather_k<<<dim3(LTOK,NBATCH),256>>>(P.nf1,P.f1,s1);
        for(int idt=0;idt<2;idt++){
            const float *aq,*ak,*av,*am,*a1,*a2,*bq,*bk,*bv,*bm,*b1,*b2;
            LW(4+idt*2,aq,ak,av,am,a1,a2);
            LW(5+idt*2,bq,bk,bv,bm,b1,b2);
            enc_layer(P,P.nf0,P.nf0,LTOK,LTOK,c0,c0,aq,ak,av,am,a1,a2);
            enc_layer(P,P.nf1,P.nf1,LTOK,LTOK,c1,c1,aq,ak,av,am,a1,a2);
            enc_layer(P,P.nf0,P.nf1,LTOK,LTOK,c0,c1,bq,bk,bv,bm,b1,b2);
            enc_layer(P,P.nf1,P.nf0,LTOK,LTOK,c1,c0,bq,bk,bv,bm,b1,b2);
        }
        scatter_k<<<dim3(LTOK,NBATCH),256>>>(out_f0,P.nf0,s0,kk);
        scatter_k<<<dim3(LTOK,NBATCH),256>>>(out_f1,P.nf1,s1,kk);
    }

    // --- blend residual for unselected tokens ---
    blend_k<<<NBATCH*LTOK,256>>>(out_f0,P.f0,0);
    blend_k<<<NBATCH*LTOK,256>>>(out_f1,P.f1,1);

    // --- tmi outputs ---
    tmi_k<<<dim3(NBATCH*NTOPIC,64),64>>>(0,out_t0);
    tmi_k<<<dim3(NBATCH*NTOPIC,64),64>>>(1,out_t1);
}